// round 1
// baseline (speedup 1.0000x reference)
#include <cuda_runtime.h>
#include <cuda_bf16.h>
#include <math.h>
#include <stdint.h>

#define BQ   1024
#define NT   50000
#define D0   83
#define HD   128
#define NL   8
#define KSEL 75
#define NC   10000
#define LDN  50048   // padded row pitch for d2 (multiple of 128)
#define SELT 512     // threads in selection kernel

// ---------------- static device scratch (allocation-free rule) ----------------
__device__ float g_t1[(size_t)NT * HD];
__device__ float g_t2[(size_t)NT * HD];
__device__ float g_t3[(size_t)NT * HD];
__device__ float g_t4[(size_t)NT * NL];
__device__ float g_h1[(size_t)BQ * HD];
__device__ float g_h2[(size_t)BQ * HD];
__device__ float g_h3[(size_t)BQ * HD];
__device__ float g_o4[(size_t)BQ * NL];
__device__ float g_tn[5 * NT];     // train-bank row norms per layer
__device__ float g_qn[5 * BQ];     // query row norms per layer
__device__ float g_d2[(size_t)BQ * LDN];
__device__ float g_tot[BQ * NL];

// ---------------- fused MLP GEMM: C[M,128] = relu(A[M,K] @ W[K,128] + b), + row norms ----------------
__global__ __launch_bounds__(256) void mlp_gemm(const float* __restrict__ A, int M, int K,
                                                const float* __restrict__ W, const float* __restrict__ bias,
                                                float* __restrict__ C, float* __restrict__ nrm)
{
    __shared__ float As[8][128];
    __shared__ float Ws[8][128];
    __shared__ float snorm[128];

    int tid = threadIdx.x;
    int tx = tid & 15, ty = tid >> 4;
    int row0 = blockIdx.x * 128;

    float acc[8][8];
#pragma unroll
    for (int i = 0; i < 8; i++)
#pragma unroll
        for (int j = 0; j < 8; j++) acc[i][j] = 0.f;

    if (tid < 128) snorm[tid] = 0.f;

    int mload = tid >> 1;
    int kb = (tid & 1) * 4;
    bool rok = (row0 + mload) < M;
    const float* aBase = A + (size_t)(row0 + mload) * K + kb;
    int wkr = tid >> 5;
    int wcol = (tid & 31) * 4;

    for (int k0 = 0; k0 < K; k0 += 8) {
#pragma unroll
        for (int j = 0; j < 4; j++) {
            int kk = k0 + kb + j;
            As[kb + j][mload] = (rok && kk < K) ? aBase[k0 + j] : 0.f;
        }
        {
            int kk = k0 + wkr;
            bool kok = kk < K;
            const float* wp = W + (size_t)kk * HD + wcol;
#pragma unroll
            for (int j = 0; j < 4; j++)
                Ws[wkr][wcol + j] = kok ? wp[j] : 0.f;
        }
        __syncthreads();
#pragma unroll
        for (int kk = 0; kk < 8; kk++) {
            float4 a0 = *(const float4*)&As[kk][ty * 4];
            float4 a1 = *(const float4*)&As[kk][64 + ty * 4];
            float4 b0 = *(const float4*)&Ws[kk][tx * 4];
            float4 b1 = *(const float4*)&Ws[kk][64 + tx * 4];
            float av[8] = {a0.x, a0.y, a0.z, a0.w, a1.x, a1.y, a1.z, a1.w};
            float bv[8] = {b0.x, b0.y, b0.z, b0.w, b1.x, b1.y, b1.z, b1.w};
#pragma unroll
            for (int i = 0; i < 8; i++)
#pragma unroll
                for (int j = 0; j < 8; j++) acc[i][j] += av[i] * bv[j];
        }
        __syncthreads();
    }

#pragma unroll
    for (int ig = 0; ig < 2; ig++)
#pragma unroll
        for (int ii = 0; ii < 4; ii++) {
            int i = ig * 4 + ii;
            int rloc = ig * 64 + ty * 4 + ii;
            int row = row0 + rloc;
            float nacc = 0.f;
            float vout[8];
#pragma unroll
            for (int jg = 0; jg < 2; jg++)
#pragma unroll
                for (int jj = 0; jj < 4; jj++) {
                    int j = jg * 4 + jj;
                    int col = jg * 64 + tx * 4 + jj;
                    float v = acc[i][j] + bias[col];
                    v = fmaxf(v, 0.f);
                    vout[j] = v;
                    nacc += v * v;
                }
            if (row < M) {
                float4 s0 = make_float4(vout[0], vout[1], vout[2], vout[3]);
                float4 s1 = make_float4(vout[4], vout[5], vout[6], vout[7]);
                *(float4*)(C + (size_t)row * HD + tx * 4) = s0;
                *(float4*)(C + (size_t)row * HD + 64 + tx * 4) = s1;
                atomicAdd(&snorm[rloc], nacc);
            }
        }
    __syncthreads();
    if (tid < 128) {
        int row = row0 + tid;
        if (row < M) nrm[row] = snorm[tid];
    }
}

// ---------------- head: softmax(A[M,128] @ W4[128,8] + b4), + row norms of probs ----------------
__global__ __launch_bounds__(128) void head_softmax(const float* __restrict__ A, const float* __restrict__ W4,
                                                    const float* __restrict__ b4,
                                                    float* __restrict__ Out, float* __restrict__ nrm, int M)
{
    int lane = threadIdx.x & 31;
    int r = blockIdx.x * 4 + (threadIdx.x >> 5);
    if (r >= M) return;
    float s[8] = {0, 0, 0, 0, 0, 0, 0, 0};
    const float* ar = A + (size_t)r * HD;
    for (int k = lane; k < HD; k += 32) {
        float a = ar[k];
        const float* wr = W4 + (size_t)k * NL;
#pragma unroll
        for (int j = 0; j < 8; j++) s[j] += a * wr[j];
    }
#pragma unroll
    for (int o = 16; o > 0; o >>= 1)
#pragma unroll
        for (int j = 0; j < 8; j++) s[j] += __shfl_xor_sync(0xFFFFFFFFu, s[j], o);
    if (lane == 0) {
        float m = -1e30f;
#pragma unroll
        for (int j = 0; j < 8; j++) { s[j] += b4[j]; m = fmaxf(m, s[j]); }
        float sum = 0.f;
#pragma unroll
        for (int j = 0; j < 8; j++) { s[j] = expf(s[j] - m); sum += s[j]; }
        float inv = 1.0f / sum;
        float nr = 0.f;
#pragma unroll
        for (int j = 0; j < 8; j++) {
            float p = s[j] * inv;
            Out[(size_t)r * NL + j] = p;
            nr += p * p;
        }
        nrm[r] = nr;
    }
}

// ---------------- row squared-norms ----------------
__global__ __launch_bounds__(128) void rownorm(const float* __restrict__ A, int M, int D, float* __restrict__ nrm)
{
    int lane = threadIdx.x & 31;
    int r = blockIdx.x * 4 + (threadIdx.x >> 5);
    if (r >= M) return;
    const float* ar = A + (size_t)r * D;
    float s = 0.f;
    for (int k = lane; k < D; k += 32) { float v = ar[k]; s += v * v; }
#pragma unroll
    for (int o = 16; o > 0; o >>= 1) s += __shfl_xor_sync(0xFFFFFFFFu, s, o);
    if (lane == 0) nrm[r] = s;
}

// ---------------- distance GEMM: d2[m,n] = max(qn[m] + tn[n] - 2*dot(Q[m],Bk[n]), 0) ----------------
__global__ __launch_bounds__(256) void dist_gemm(const float* __restrict__ Q, const float* __restrict__ Bk,
                                                 const float* __restrict__ qn, const float* __restrict__ tn,
                                                 int K, float* __restrict__ D2)
{
    __shared__ float Qs[8][128];
    __shared__ float Bs[8][128];
    int tid = threadIdx.x, tx = tid & 15, ty = tid >> 4;
    int n0 = blockIdx.x * 128, m0 = blockIdx.y * 128;

    float acc[8][8];
#pragma unroll
    for (int i = 0; i < 8; i++)
#pragma unroll
        for (int j = 0; j < 8; j++) acc[i][j] = 0.f;

    int lm = tid >> 1;
    int kb = (tid & 1) * 4;
    const float* qBase = Q + (size_t)(m0 + lm) * K + kb;       // m0+lm < 1024 always
    bool nok = (n0 + lm) < NT;
    const float* bBase = Bk + (size_t)(n0 + lm) * K + kb;

    for (int k0 = 0; k0 < K; k0 += 8) {
#pragma unroll
        for (int j = 0; j < 4; j++) {
            int kk = k0 + kb + j;
            bool kok = kk < K;
            Qs[kb + j][lm] = kok ? qBase[k0 + j] : 0.f;
            Bs[kb + j][lm] = (kok && nok) ? bBase[k0 + j] : 0.f;
        }
        __syncthreads();
#pragma unroll
        for (int kk = 0; kk < 8; kk++) {
            float4 a0 = *(const float4*)&Qs[kk][ty * 4];
            float4 a1 = *(const float4*)&Qs[kk][64 + ty * 4];
            float4 b0 = *(const float4*)&Bs[kk][tx * 4];
            float4 b1 = *(const float4*)&Bs[kk][64 + tx * 4];
            float av[8] = {a0.x, a0.y, a0.z, a0.w, a1.x, a1.y, a1.z, a1.w};
            float bv[8] = {b0.x, b0.y, b0.z, b0.w, b1.x, b1.y, b1.z, b1.w};
#pragma unroll
            for (int i = 0; i < 8; i++)
#pragma unroll
                for (int j = 0; j < 8; j++) acc[i][j] += av[i] * bv[j];
        }
        __syncthreads();
    }

#pragma unroll
    for (int ig = 0; ig < 2; ig++)
#pragma unroll
        for (int ii = 0; ii < 4; ii++) {
            int i = ig * 4 + ii;
            int m = m0 + ig * 64 + ty * 4 + ii;
            float q2 = qn[m];
#pragma unroll
            for (int jg = 0; jg < 2; jg++)
#pragma unroll
                for (int jj = 0; jj < 4; jj++) {
                    int j = jg * 4 + jj;
                    int n = n0 + jg * 64 + tx * 4 + jj;
                    if (n < NT) {
                        float d = q2 + tn[n] - 2.0f * acc[i][j];
                        D2[(size_t)m * LDN + n] = fmaxf(d, 0.f);
                    }
                }
        }
}

// ---------------- per-query exact top-75 radix select + nonconformity accumulation ----------------
__global__ __launch_bounds__(SELT) void select_accum(const float* __restrict__ D2,
                                                     const int* __restrict__ labels,
                                                     float* __restrict__ tot, int layer)
{
    extern __shared__ unsigned int keys[];   // NT entries
    __shared__ unsigned int hist[256];
    __shared__ unsigned int wsum[8];
    __shared__ unsigned int sel_digit, sel_knew;
    __shared__ int tieIdx[2048];
    __shared__ int tieCnt;
    __shared__ float sTot, sCls[NL];

    int tid = threadIdx.x;
    int b = blockIdx.x;
    const float* row = D2 + (size_t)b * LDN;

#pragma unroll 16
    for (int n = tid; n < NT; n += SELT) keys[n] = __float_as_uint(row[n]);
    if (tid == 0) { tieCnt = 0; sTot = 0.f; }
    if (tid < NL) sCls[tid] = 0.f;
    __syncthreads();

    unsigned int prefix = 0, mask = 0, kneed = KSEL;
    for (int pass = 0; pass < 4; pass++) {
        int shift = 24 - 8 * pass;
        if (tid < 256) hist[tid] = 0u;
        __syncthreads();
#pragma unroll 8
        for (int n = tid; n < NT; n += SELT) {
            unsigned int k = keys[n];
            if ((k & mask) == prefix) atomicAdd(&hist[(k >> shift) & 255u], 1u);
        }
        __syncthreads();
        unsigned int v = 0, sc = 0;
        unsigned int lane = tid & 31, wrp = tid >> 5;
        if (tid < 256) {
            v = hist[tid];
            sc = v;
#pragma unroll
            for (int o = 1; o < 32; o <<= 1) {
                unsigned int t = __shfl_up_sync(0xFFFFFFFFu, sc, o);
                if (lane >= (unsigned)o) sc += t;
            }
            if (lane == 31) wsum[wrp] = sc;
        }
        __syncthreads();
        if (tid < 8) {
            unsigned int s2 = wsum[tid];
#pragma unroll
            for (int o = 1; o < 8; o <<= 1) {
                unsigned int q = __shfl_up_sync(0xFFu, s2, o);
                if (tid >= o) s2 += q;
            }
            wsum[tid] = s2;
        }
        __syncthreads();
        if (tid < 256) {
            unsigned int incl = sc + (wrp ? wsum[wrp - 1] : 0u);
            unsigned int excl = incl - v;
            if (excl < kneed && incl >= kneed) { sel_digit = (unsigned)tid; sel_knew = kneed - excl; }
        }
        __syncthreads();
        prefix |= sel_digit << shift;
        mask |= 0xFFu << shift;
        kneed = sel_knew;
        __syncthreads();
    }
    unsigned int T = prefix;   // exact bits of the k-th smallest d2; kneed = #ties to include

#pragma unroll 8
    for (int n = tid; n < NT; n += SELT) {
        unsigned int k = keys[n];
        if (k < T) {
            float d2v = __uint_as_float(k);
            if (d2v > 0.f) {
                float w = 1.0f / sqrtf(d2v);
                atomicAdd(&sTot, w);
                atomicAdd(&sCls[labels[n]], w);
            }
        } else if (k == T) {
            int p = atomicAdd(&tieCnt, 1);
            if (p < 2048) tieIdx[p] = n;
        }
    }
    __syncthreads();

    if (tid == 0) {
        int cnt = tieCnt;
        if (cnt > 2048) cnt = 2048;
        float d2v = __uint_as_float(T);
        float w = (d2v > 0.f) ? (1.0f / sqrtf(d2v)) : 0.f;
        int need = (int)kneed;
        if (need > cnt) need = cnt;
        if (cnt == need) {
            for (int i = 0; i < cnt; i++) sCls[labels[tieIdx[i]]] += w;
        } else {
            // ties broken by lowest index (matches top_k semantics)
            int last = -1;
            for (int s = 0; s < need; s++) {
                int best = 0x7FFFFFFF;
                for (int i = 0; i < cnt; i++) {
                    int vv = tieIdx[i];
                    if (vv > last && vv < best) best = vv;
                }
                sCls[labels[best]] += w;
                last = best;
            }
        }
        sTot += w * (float)need;
    }
    __syncthreads();

    if (tid < NL) {
        float contrib = sTot - sCls[tid];
        if (layer == 0) tot[b * NL + tid] = contrib;
        else            tot[b * NL + tid] += contrib;
    }
}

// ---------------- empirical p-value ----------------
__global__ __launch_bounds__(256) void pvalue_kernel(const float* __restrict__ tot,
                                                     const float* __restrict__ cali,
                                                     float* __restrict__ out)
{
    __shared__ int cnt[NL];
    int b = blockIdx.x, tid = threadIdx.x;
    if (tid < NL) cnt[tid] = 0;
    __syncthreads();
    float tv[8];
#pragma unroll
    for (int j = 0; j < 8; j++) tv[j] = tot[b * NL + j];
    int c[8] = {0, 0, 0, 0, 0, 0, 0, 0};
    for (int i = tid; i < NC; i += 256) {
        float cv = cali[i];
#pragma unroll
        for (int j = 0; j < 8; j++) c[j] += (cv >= tv[j]) ? 1 : 0;
    }
#pragma unroll
    for (int j = 0; j < 8; j++) atomicAdd(&cnt[j], c[j]);
    __syncthreads();
    if (tid < NL) out[b * NL + tid] = (float)cnt[tid] / (float)NC;
}

// ---------------- driver ----------------
extern "C" void kernel_launch(void* const* d_in, const int* in_sizes, int n_in,
                              void* d_out, int out_size)
{
    const float* x    = (const float*)d_in[0];
    const float* trx  = (const float*)d_in[1];
    const int*   lab  = (const int*)  d_in[2];
    const float* cali = (const float*)d_in[3];
    const float* W1 = (const float*)d_in[4];  const float* b1 = (const float*)d_in[5];
    const float* W2 = (const float*)d_in[6];  const float* b2 = (const float*)d_in[7];
    const float* W3 = (const float*)d_in[8];  const float* b3 = (const float*)d_in[9];
    const float* W4 = (const float*)d_in[10]; const float* b4 = (const float*)d_in[11];
    float* out = (float*)d_out;

    float *t1, *t2, *t3, *t4, *h1, *h2, *h3, *o4, *tn, *qn, *d2, *tot;
    cudaGetSymbolAddress((void**)&t1, g_t1);
    cudaGetSymbolAddress((void**)&t2, g_t2);
    cudaGetSymbolAddress((void**)&t3, g_t3);
    cudaGetSymbolAddress((void**)&t4, g_t4);
    cudaGetSymbolAddress((void**)&h1, g_h1);
    cudaGetSymbolAddress((void**)&h2, g_h2);
    cudaGetSymbolAddress((void**)&h3, g_h3);
    cudaGetSymbolAddress((void**)&o4, g_o4);
    cudaGetSymbolAddress((void**)&tn, g_tn);
    cudaGetSymbolAddress((void**)&qn, g_qn);
    cudaGetSymbolAddress((void**)&d2, g_d2);
    cudaGetSymbolAddress((void**)&tot, g_tot);

    cudaFuncSetAttribute(select_accum, cudaFuncAttributeMaxDynamicSharedMemorySize,
                         NT * (int)sizeof(unsigned int));

    int gT = (NT + 127) / 128;   // 391

    // train-side feature banks (+ fused row norms)
    mlp_gemm<<<gT, 256>>>(trx, NT, D0, W1, b1, t1, tn + 1 * NT);
    mlp_gemm<<<gT, 256>>>(t1, NT, HD, W2, b2, t2, tn + 2 * NT);
    mlp_gemm<<<gT, 256>>>(t2, NT, HD, W3, b3, t3, tn + 3 * NT);
    head_softmax<<<(NT + 3) / 4, 128>>>(t3, W4, b4, t4, tn + 4 * NT, NT);
    rownorm<<<(NT + 3) / 4, 128>>>(trx, NT, D0, tn + 0 * NT);

    // query-side MLP (+ fused row norms)
    mlp_gemm<<<BQ / 128, 256>>>(x, BQ, D0, W1, b1, h1, qn + 1 * BQ);
    mlp_gemm<<<BQ / 128, 256>>>(h1, BQ, HD, W2, b2, h2, qn + 2 * BQ);
    mlp_gemm<<<BQ / 128, 256>>>(h2, BQ, HD, W3, b3, h3, qn + 3 * BQ);
    head_softmax<<<BQ / 4, 128>>>(h3, W4, b4, o4, qn + 4 * BQ, BQ);
    rownorm<<<BQ / 4, 128>>>(x, BQ, D0, qn + 0 * BQ);

    const float* Qarr[5] = {x, h1, h2, h3, o4};
    const float* Barr[5] = {trx, t1, t2, t3, t4};
    int Karr[5] = {D0, HD, HD, HD, NL};

    for (int l = 0; l < 5; l++) {
        dist_gemm<<<dim3(gT, BQ / 128), 256>>>(Qarr[l], Barr[l], qn + l * BQ, tn + l * NT, Karr[l], d2);
        select_accum<<<BQ, SELT, NT * sizeof(unsigned int)>>>(d2, lab, tot, l);
    }

    pvalue_kernel<<<BQ, 256>>>(tot, cali, out);
}